// round 1
// baseline (speedup 1.0000x reference)
#include <cuda_runtime.h>
#include <cuda_bf16.h>
#include <math.h>

// BidirectionalALiBi: out[h, i, j] = |j - i| * m
//   m = alpha[h] if (i==0 || j==0)
//       gamma[h] if j > i
//       beta[h]  if j < i
//       (diag j==i: dist=0, value 0 regardless)
//
// Pure store-bandwidth-bound: 16*2048*2048*4 = 268 MB written, ~0 read.
// One block per (h, i) row; each thread writes one float4 (STG.128).

__global__ void __launch_bounds__(512, 4)
alibi_kernel(const float* __restrict__ alpha,
             const float* __restrict__ beta,
             const float* __restrict__ gamma,
             float* __restrict__ out,
             int S, int log2S)
{
    const int row = blockIdx.x;        // row = h * S + i
    const int h = row >> log2S;
    const int i = row - (h << log2S);

    const float a = __ldg(&alpha[h]);
    const float b = __ldg(&beta[h]);
    const float g = __ldg(&gamma[h]);

    // Row-uniform simplification: if i == 0, every element uses alpha.
    const bool edge_row = (i == 0);

    float4* __restrict__ orow =
        reinterpret_cast<float4*>(out + (size_t)row * (size_t)S);

    const int j0 = threadIdx.x << 2;   // 4 elements per thread
    const float fi = (float)i;

    float4 v;
    float* vp = reinterpret_cast<float*>(&v);

#pragma unroll
    for (int k = 0; k < 4; ++k) {
        const int j = j0 + k;
        const float d = fabsf((float)j - fi);
        float m;
        if (edge_row) {
            m = a;
        } else {
            m = (j > i) ? g : b;       // j < i -> beta; j == i irrelevant (d=0)
            if (j == 0) m = a;         // edge column overrides
        }
        vp[k] = d * m;
    }

    orow[threadIdx.x] = v;
}

extern "C" void kernel_launch(void* const* d_in, const int* in_sizes, int n_in,
                              void* d_out, int out_size)
{
    const float* alpha = (const float*)d_in[0];
    const float* beta  = (const float*)d_in[1];
    const float* gamma = (const float*)d_in[2];
    float* out = (float*)d_out;

    const int H = in_sizes[0];                 // 16
    // out_size = H * S * S  ->  S = sqrt(out_size / H)
    long long ss = (long long)out_size / H;
    int S = (int)(sqrt((double)ss) + 0.5);

    int log2S = 0;
    while ((1 << log2S) < S) ++log2S;          // S is a power of two (2048)

    const int threads = S / 4;                 // 512 for S=2048
    const int blocks = H * S;                  // 32768

    alibi_kernel<<<blocks, threads>>>(alpha, beta, gamma, out, S, log2S);
}